// round 8
// baseline (speedup 1.0000x reference)
#include <cuda_runtime.h>
#include <cuda_bf16.h>
#include <stdint.h>

#define NCORR    10000
#define NPIX     16384
#define MTHETA   1184                  // θ-grid; ×4 n-chunks = 4736 tasks = #warps
#define NBLK     148
#define LOG2E    1.4426950408889634
#define RSQRT2   0.70710678118654752f
#define RSQRT6   0.40824829046386302f
#define SQRT2F   1.41421356237309505f
#define TWOPI    6.283185307179586476925286766559

typedef unsigned long long ull;

__device__ __forceinline__ ull pk(float lo, float hi) {
    ull r; asm("mov.b64 %0, {%1,%2};" : "=l"(r) : "f"(lo), "f"(hi)); return r;
}
__device__ __forceinline__ void upk(ull v, float& lo, float& hi) {
    asm("mov.b64 {%0,%1}, %2;" : "=f"(lo), "=f"(hi) : "l"(v));
}
__device__ __forceinline__ ull f2mul(ull a, ull b) {
    ull d; asm("mul.rn.f32x2 %0, %1, %2;" : "=l"(d) : "l"(a), "l"(b)); return d;
}
__device__ __forceinline__ ull f2add(ull a, ull b) {
    ull d; asm("add.rn.f32x2 %0, %1, %2;" : "=l"(d) : "l"(a), "l"(b)); return d;
}
__device__ __forceinline__ ull f2fma(ull a, ull b, ull c) {
    ull d; asm("fma.rn.f32x2 %0, %1, %2, %3;" : "=l"(d) : "l"(a), "l"(b), "l"(c)); return d;
}
__device__ __forceinline__ float ex2(float x) {
    float r; asm("ex2.approx.f32 %0, %1;" : "=f"(r) : "f"(x)); return r;
}

// ---------------- device scratch ----------------
__device__ float  g_modT[3][NCORR];
__device__ float  g_demT[3][NCORR];
__device__ float  g_Mre[10000], g_Mim[10000];    // DFT-100 matrix W_100^{-xy}
__device__ float  g_TWre[10000], g_TWim[10000];  // twiddle W_10000^{-xy}
__device__ float  g_T[6][2][10000];              // fwd stage1 (twiddled): T[b][c]
__device__ float  g_F[6][2][10000];              // fwd stage2: F[c][d], k=c+100d
__device__ float  g_V[3][2][10000];              // inv stage1: V[c][g]
__device__ float  g_raw[3][NCORR];
__device__ double g_sums[6];                     // [0..2] Mod col sums, [3..5] Dem col sums
__device__ double g_bs1[3][10], g_bs2[3][10];    // corr moment partials
__device__ __align__(16) float2 g_ps[MTHETA][4]; // per-(theta, n-chunk) partial (S, W)
__device__ int    g_sync;                        // monotonic ticket barrier (never reset)

// Monotonic-ticket grid barrier: safe across graph replays (no reset needed).
// Valid because all 148 blocks are resident (148 blocks <= 148 SMs).
__device__ __forceinline__ void grid_sync() {
    __syncthreads();
    if (threadIdx.x == 0) {
        __threadfence();
        int t = atomicAdd(&g_sync, 1);
        int target = (t / NBLK + 1) * NBLK;
        while (*(volatile int*)&g_sync < target) {}
        __threadfence();
    }
    __syncthreads();
}

__global__ void __launch_bounds__(1024, 1)
mega_kernel(const float* __restrict__ gt, const float* __restrict__ Mod,
            const float* __restrict__ Dem, float* __restrict__ out) {
    extern __shared__ __align__(16) char smem_raw[];
    const int tid = threadIdx.x, bid = blockIdx.x;

    // ======== phase A: transpose SoA + DFT/twiddle tables + fp64 column sums ========
    {
        const int idx = bid * 1024 + tid;
        if (idx < 30000) {
            float v = Mod[idx];
            g_modT[idx % 3][idx / 3] = v;
        } else if (idx < 60000) {
            int i2 = idx - 30000;
            float v = Dem[i2];
            g_demT[i2 % 3][i2 / 3] = v;
        } else if (idx < 80000) {
            int q = idx - 60000;
            int p = q % 10000;
            int x = p / 100, y = p % 100;
            double s, c;
            if (q < 10000) {                       // M = W_100^{-xy}
                int r = (x * y) % 100;
                sincos(-TWOPI * (double)r / 100.0, &s, &c);
                g_Mre[p] = (float)c; g_Mim[p] = (float)s;
            } else {                               // TW = W_10000^{-xy}
                int r = x * y;                     // < 10000
                sincos(-TWOPI * (double)r / 10000.0, &s, &c);
                g_TWre[p] = (float)c; g_TWim[p] = (float)s;
            }
        }
        if (bid >= 1 && bid <= 6) {                // blocks 1..6: 6 column sums (fp64)
            const int b = bid - 1, k = b % 3;
            const float* src = (b < 3) ? Mod : Dem;
            double s = 0.0;
            for (int i = tid; i < NCORR; i += 1024) s += (double)src[i * 3 + k];
            double* sh = reinterpret_cast<double*>(smem_raw);
            sh[tid] = s; __syncthreads();
            for (int o = 512; o; o >>= 1) {
                if (tid < o) sh[tid] += sh[tid + o];
                __syncthreads();
            }
            if (tid == 0) g_sums[b] = sh[0];
        }
    }
    grid_sync();   // 1

    // ======== phase B1: forward stage 1 — S[b][c] = sum_a src[100a+b]·M[a][c], then ·TW ========
    if (bid < 60) {
        const int t = bid / 10, c0 = (bid % 10) * 10;
        const float* src = (t < 3) ? g_modT[t] : g_demT[t - 3];
        float* sG   = reinterpret_cast<float*>(smem_raw);      // [10000]
        float* sMre = sG + 10000;                              // [100][10]
        float* sMim = sMre + 1000;
        for (int i = tid; i < 10000; i += 1024) sG[i] = src[i];
        if (tid < 1000) {
            int a = tid / 10, cc = tid % 10;
            sMre[tid] = g_Mre[a * 100 + c0 + cc];
            sMim[tid] = g_Mim[a * 100 + c0 + cc];
        }
        __syncthreads();
        if (tid < 1000) {
            const int b = tid / 10, cc = tid % 10;
            float sre = 0.f, sim = 0.f;
#pragma unroll 5
            for (int a = 0; a < 100; a++) {
                float g = sG[a * 100 + b];
                sre = fmaf(g, sMre[a * 10 + cc], sre);
                sim = fmaf(g, sMim[a * 10 + cc], sim);
            }
            const int c = c0 + cc;
            float twre = g_TWre[b * 100 + c], twim = g_TWim[b * 100 + c];
            g_T[t][0][b * 100 + c] = sre * twre - sim * twim;
            g_T[t][1][b * 100 + c] = fmaf(sre, twim, sim * twre);
        }
    }
    grid_sync();   // 2

    // ======== phase B2: forward stage 2 — F[c][d] = sum_b T[b][c]·M[b][d] ========
    if (bid < 60) {
        const int t = bid / 10, d0 = (bid % 10) * 10;
        float* sTre = reinterpret_cast<float*>(smem_raw);      // [25][100] chunk
        float* sTim = sTre + 2500;
        float* sMre = sTim + 2500;                             // [100][10]
        float* sMim = sMre + 1000;
        if (tid < 1000) {
            int b = tid / 10, dd = tid % 10;
            sMre[tid] = g_Mre[b * 100 + d0 + dd];
            sMim[tid] = g_Mim[b * 100 + d0 + dd];
        }
        float xre = 0.f, xim = 0.f;
        const int c = tid / 10, dd = tid % 10;
        for (int chunk = 0; chunk < 4; chunk++) {
            __syncthreads();
            for (int i = tid; i < 2500; i += 1024) {
                int bl = i / 100, c2 = i % 100;
                sTre[i] = g_T[t][0][(chunk * 25 + bl) * 100 + c2];
                sTim[i] = g_T[t][1][(chunk * 25 + bl) * 100 + c2];
            }
            __syncthreads();
            if (tid < 1000) {
#pragma unroll 5
                for (int bl = 0; bl < 25; bl++) {
                    int b = chunk * 25 + bl;
                    float tre = sTre[bl * 100 + c], tim = sTim[bl * 100 + c];
                    float mre = sMre[b * 10 + dd], mim = sMim[b * 10 + dd];
                    xre = fmaf(tre, mre, xre); xre = fmaf(-tim, mim, xre);
                    xim = fmaf(tre, mim, xim); xim = fmaf(tim, mre, xim);
                }
            }
        }
        if (tid < 1000) {
            g_F[t][0][c * 100 + d0 + dd] = xre;
            g_F[t][1][c * 100 + d0 + dd] = xim;
        }
    }
    grid_sync();   // 3

    // ======== phase B3: P = conj(Fm)·Fd ; U[c][g] = sum_d P[c][d]·conj(M)[d][g] ; V = U·conj(TW) ========
    if (bid < 30) {
        const int j = bid / 10, c0 = (bid % 10) * 10;
        float* sPre = reinterpret_cast<float*>(smem_raw);      // [10][100]
        float* sPim = sPre + 1000;
        if (tid < 1000) {
            int cc = tid / 100, d = tid % 100;
            int ci = (c0 + cc) * 100 + d;
            float fmre = g_F[j][0][ci],     fmim = g_F[j][1][ci];
            float fdre = g_F[j + 3][0][ci], fdim = g_F[j + 3][1][ci];
            sPre[tid] = fmaf(fmre, fdre, fmim * fdim);         // conj(Fm)*Fd
            sPim[tid] = fmaf(fmre, fdim, -fmim * fdre);
        }
        __syncthreads();
        if (tid < 1000) {
            const int cc = tid / 100, g = tid % 100;
            float ure = 0.f, uim = 0.f;
#pragma unroll 4
            for (int d = 0; d < 100; d++) {
                float pre = sPre[cc * 100 + d], pim = sPim[cc * 100 + d];
                float mre = __ldg(&g_Mre[d * 100 + g]);
                float mim = __ldg(&g_Mim[d * 100 + g]);
                // · conj(M): re += pre*mre + pim*mim ; im += pim*mre - pre*mim
                ure = fmaf(pre, mre, ure); ure = fmaf(pim, mim, ure);
                uim = fmaf(pim, mre, uim); uim = fmaf(-pre, mim, uim);
            }
            const int c = c0 + cc;
            float twre = g_TWre[c * 100 + g], twim = g_TWim[c * 100 + g];
            // · conj(TW)
            g_V[j][0][c * 100 + g] = fmaf(ure, twre, uim * twim);
            g_V[j][1][c * 100 + g] = fmaf(uim, twre, -ure * twim);
        }
    }
    grid_sync();   // 4

    // ======== phase B4: raw[g+100h] = (1/N) sum_c (Vre[c][g]·Mre[c][h] + Vim[c][g]·Mim[c][h]) ========
    if (bid < 30) {
        const int j = bid / 10, g0 = (bid % 10) * 10;
        float* sVre = reinterpret_cast<float*>(smem_raw);      // [100][10]
        float* sVim = sVre + 1000;
        __shared__ double sm1[32], sm2[32];
        if (tid < 1000) {
            int c = tid / 10, gg = tid % 10;
            sVre[tid] = g_V[j][0][c * 100 + g0 + gg];
            sVim[tid] = g_V[j][1][c * 100 + g0 + gg];
        }
        __syncthreads();
        double ms = 0.0, ms2 = 0.0;
        if (tid < 1000) {
            const int gg = tid / 100, h = tid % 100;
            float acc = 0.f;
#pragma unroll 4
            for (int c = 0; c < 100; c++) {
                float vre = sVre[c * 10 + gg], vim = sVim[c * 10 + gg];
                acc = fmaf(vre, __ldg(&g_Mre[c * 100 + h]), acc);
                acc = fmaf(vim, __ldg(&g_Mim[c * 100 + h]), acc);
            }
            float raw = acc * 1e-4f;
            g_raw[j][(g0 + gg) + 100 * h] = raw;
            ms = (double)raw; ms2 = ms * ms;
        }
        // block moment reduce (fixed-order: shuffle tree + smem tree)
#pragma unroll
        for (int o = 16; o; o >>= 1) {
            ms  += __shfl_xor_sync(0xffffffffu, ms,  o);
            ms2 += __shfl_xor_sync(0xffffffffu, ms2, o);
        }
        if ((tid & 31) == 0) { sm1[tid >> 5] = ms; sm2[tid >> 5] = ms2; }
        __syncthreads();
        if (tid < 32) {
            double s  = sm1[tid], sq = sm2[tid];
#pragma unroll
            for (int o = 16; o; o >>= 1) {
                s  += __shfl_xor_sync(0xffffffffu, s,  o);
                sq += __shfl_xor_sync(0xffffffffu, sq, o);
            }
            if (tid == 0) { g_bs1[j][bid % 10] = s; g_bs2[j][bid % 10] = sq; }
        }
    }
    grid_sync();   // 5

    // ======== phase D: every block folds stats redundantly ========
    __shared__ float sh_scale[3], sh_mean[3], sh_amb[3];
    {
        const int w = tid >> 5, lane = tid & 31;
        if (w < 3) {
            double s1 = (lane < 10) ? g_bs1[w][lane] : 0.0;
            double s2 = (lane < 10) ? g_bs2[w][lane] : 0.0;
#pragma unroll
            for (int o = 16; o; o >>= 1) {
                s1 += __shfl_xor_sync(0xffffffffu, s1, o);
                s2 += __shfl_xor_sync(0xffffffffu, s2, o);
            }
            if (lane == 0) {
                double mean = s1 / NCORR;
                double var  = (s2 - s1 * s1 / NCORR) / (NCORR - 1);
                double sgn  = (g_sums[w] < 0.0) ? -1.0 : 1.0;
                sh_scale[w] = (float)(sgn * LOG2E / sqrt(var));
                sh_mean[w]  = (float)mean;
            }
        }
        if (tid >= 96 && tid < 99) sh_amb[tid - 96] = (float)(1.0e6 * g_sums[3 + (tid - 96)]);
    }
    __syncthreads();

    // ======== phase E: build SoA templates (u, v) into smem ========
    float* s_u = reinterpret_cast<float*>(smem_raw);
    float* s_v = s_u + 10048;
    {
        const float sc0 = sh_scale[0], sc1 = sh_scale[1], sc2 = sh_scale[2];
        const float mv0 = sh_mean[0],  mv1 = sh_mean[1],  mv2 = sh_mean[2];
        for (int n = tid; n < NCORR; n += 1024) {
            float c0 = sc0 * (g_raw[0][n] - mv0);
            float c1 = sc1 * (g_raw[1][n] - mv1);
            float c2 = sc2 * (g_raw[2][n] - mv2);
            s_u[n] = (c0 - c1) * RSQRT2;
            s_v[n] = (c0 + c1 - 2.f * c2) * RSQRT6;
        }
    }
    __syncthreads();

    // ======== phase F: theta-grid decode — exactly 1 task per warp ========
    {
        const int lane = tid & 31;
        const int task = bid * 32 + (tid >> 5);
        const int j = task >> 2, chunk = task & 3;
        const int base = chunk * 2500;
        float sn_, cs_;
        sincosf((float)((double)j * (TWOPI / MTHETA)), &sn_, &cs_);
        const float p = SQRT2F * cs_, q = SQRT2F * sn_;
        const ull pp = pk(p, p), qq = pk(q, q);
        const ull c128 = pk(128.f, 128.f);

        ull sA = 0ull, sB = 0ull, wA = 0ull, wB = 0ull;
        const int nb = base + 4 * lane;
        ull nfA = pk((float)nb, (float)(nb + 1));
        ull nfB = pk((float)(nb + 2), (float)(nb + 3));
        const ulonglong2* pu = reinterpret_cast<const ulonglong2*>(&s_u[nb]);
        const ulonglong2* pv = reinterpret_cast<const ulonglong2*>(&s_v[nb]);

#pragma unroll 4
        for (int it = 0; it < 19; it++) {         // 19*128 = 2432 of 2500
            ulonglong2 U = pu[it * 32];
            ulonglong2 V = pv[it * 32];
            ull zA = f2fma(pp, U.x, f2mul(qq, V.x));
            ull zB = f2fma(pp, U.y, f2mul(qq, V.y));
            float a, b;
            upk(zA, a, b); ull eA = pk(ex2(a), ex2(b));
            upk(zB, a, b); ull eB = pk(ex2(a), ex2(b));
            sA = f2add(sA, eA);  sB = f2add(sB, eB);
            wA = f2fma(eA, nfA, wA); wB = f2fma(eB, nfB, wB);
            nfA = f2add(nfA, c128);  nfB = f2add(nfB, c128);
        }
        if (lane < 17) {                          // tail: 68 samples
            const int n = base + 2432 + 4 * lane;
            ulonglong2 U = *reinterpret_cast<const ulonglong2*>(&s_u[n]);
            ulonglong2 V = *reinterpret_cast<const ulonglong2*>(&s_v[n]);
            ull ntA = pk((float)n, (float)(n + 1));
            ull ntB = pk((float)(n + 2), (float)(n + 3));
            ull zA = f2fma(pp, U.x, f2mul(qq, V.x));
            ull zB = f2fma(pp, U.y, f2mul(qq, V.y));
            float a, b;
            upk(zA, a, b); ull eA = pk(ex2(a), ex2(b));
            upk(zB, a, b); ull eB = pk(ex2(a), ex2(b));
            sA = f2add(sA, eA);  sB = f2add(sB, eB);
            wA = f2fma(eA, ntA, wA); wB = f2fma(eB, ntB, wB);
        }
        float a, b, s, w;
        ull st = f2add(sA, sB), wt = f2add(wA, wB);
        upk(st, a, b); s = a + b;
        upk(wt, a, b); w = a + b;
#pragma unroll
        for (int o = 16; o; o >>= 1) {
            s += __shfl_xor_sync(0xffffffffu, s, o);
            w += __shfl_xor_sync(0xffffffffu, w, o);
        }
        if (lane == 0) g_ps[j][chunk] = make_float2(s, w);
    }
    grid_sync();   // 6

    // ======== phase G: gather per pixel (atan2 + lerp) ========
    {
        const float amb0 = sh_amb[0], amb1 = sh_amb[1], amb2 = sh_amb[2];
        const float inv_dt = (float)(MTHETA / TWOPI);
        const int px = bid * 1024 + tid;
        if (px < NPIX) {
            int idx = (int)rintf(gt[px]);
            idx = min(max(idx, 0), NCORR - 1);
            float x = __ldcg(&g_raw[0][idx]) + amb0;
            float y = __ldcg(&g_raw[1][idx]) + amb1;
            float z = __ldcg(&g_raw[2][idx]) + amb2;
            float pv = (x - y);
            float qv = (x + y - 2.f * z) * (RSQRT6 / RSQRT2);
            float th = atan2f(qv, pv);
            if (th < 0.f) th += (float)TWOPI;
            float g = th * inv_dt;
            int j0 = (int)g;
            float f = g - (float)j0;
            if (j0 >= MTHETA) j0 -= MTHETA;
            int j1 = j0 + 1; if (j1 >= MTHETA) j1 -= MTHETA;
            const float4* q0 = reinterpret_cast<const float4*>(&g_ps[j0][0]);
            const float4* q1 = reinterpret_cast<const float4*>(&g_ps[j1][0]);
            float4 u0 = __ldcg(&q0[0]), u1 = __ldcg(&q0[1]);
            float4 v0 = __ldcg(&q1[0]), v1 = __ldcg(&q1[1]);
            float S0 = u0.x + u0.z + u1.x + u1.z;
            float W0 = u0.y + u0.w + u1.y + u1.w;
            float S1 = v0.x + v0.z + v1.x + v1.z;
            float W1 = v0.y + v0.w + v1.y + v1.w;
            float F0 = W0 / S0, F1 = W1 / S1;
            out[px] = fmaf(f, F1 - F0, F0);
        }
    }
}

extern "C" void kernel_launch(void* const* d_in, const int* in_sizes, int n_in,
                              void* d_out, int out_size) {
    const float* gt  = (const float*)d_in[0];
    const float* Mod = (const float*)d_in[1];
    const float* Dem = (const float*)d_in[2];
    float* out = (float*)d_out;

    int smem = 98304;   // max phase use ~80.4KB (templates); 148 blocks -> 1/SM, all resident
    cudaFuncSetAttribute(mega_kernel, cudaFuncAttributeMaxDynamicSharedMemorySize, smem);
    mega_kernel<<<NBLK, 1024, smem>>>(gt, Mod, Dem, out);
}

// round 10
// speedup vs baseline: 1.0005x; 1.0005x over previous
#include <cuda_runtime.h>
#include <cuda_bf16.h>
#include <stdint.h>

#define NCORR    10000
#define NPIX     16384
#define MTHETA   1184                  // θ-grid; ×4 n-chunks = 4736 tasks = #warps
#define NBLK     148
#define LOG2E    1.4426950408889634
#define RSQRT2   0.70710678118654752f
#define RSQRT6   0.40824829046386302f
#define SQRT2F   1.41421356237309505f
#define TWOPI    6.283185307179586476925286766559

typedef unsigned long long ull;

__device__ __forceinline__ ull pk(float lo, float hi) {
    ull r; asm("mov.b64 %0, {%1,%2};" : "=l"(r) : "f"(lo), "f"(hi)); return r;
}
__device__ __forceinline__ void upk(ull v, float& lo, float& hi) {
    asm("mov.b64 {%0,%1}, %2;" : "=f"(lo), "=f"(hi) : "l"(v));
}
__device__ __forceinline__ ull f2mul(ull a, ull b) {
    ull d; asm("mul.rn.f32x2 %0, %1, %2;" : "=l"(d) : "l"(a), "l"(b)); return d;
}
__device__ __forceinline__ ull f2add(ull a, ull b) {
    ull d; asm("add.rn.f32x2 %0, %1, %2;" : "=l"(d) : "l"(a), "l"(b)); return d;
}
__device__ __forceinline__ ull f2fma(ull a, ull b, ull c) {
    ull d; asm("fma.rn.f32x2 %0, %1, %2, %3;" : "=l"(d) : "l"(a), "l"(b), "l"(c)); return d;
}
__device__ __forceinline__ float ex2(float x) {
    float r; asm("ex2.approx.f32 %0, %1;" : "=f"(r) : "f"(x)); return r;
}

// ---------------- device scratch ----------------
__device__ float  g_modT[3][NCORR];
__device__ float  g_demT[3][NCORR];
__device__ float  g_Mre[10000], g_Mim[10000];    // DFT-100 matrix W_100^{-xy}
__device__ float  g_TWre[10000], g_TWim[10000];  // twiddle W_10000^{-xy}
__device__ float  g_T[6][2][10000];              // fwd stage1 (twiddled): T[b][c]
__device__ float  g_F[6][2][10000];              // fwd stage2: F[c][d], k=c+100d
__device__ float  g_V[3][2][10000];              // inv stage1: V[c][g]
__device__ float  g_raw[3][NCORR];
__device__ double g_s6[6][5];                    // column-sum partials (30 blocks)
__device__ double g_bs1[3][10], g_bs2[3][10];    // corr moment partials
__device__ __align__(16) float2 g_ps[MTHETA][4]; // per-(theta, n-chunk) partial (S, W)
__device__ int    g_sync;                        // monotonic ticket barrier (never reset)

// Monotonic-ticket grid barrier: safe across graph replays (no reset needed).
// Valid because all 148 blocks are resident (148 blocks <= 148 SMs).
__device__ __forceinline__ void grid_sync() {
    __syncthreads();
    if (threadIdx.x == 0) {
        __threadfence();
        int t = atomicAdd(&g_sync, 1);
        int target = (t / NBLK + 1) * NBLK;
        while (*(volatile int*)&g_sync < target) {}
        __threadfence();
    }
    __syncthreads();
}

__global__ void __launch_bounds__(1024, 1)
mega_kernel(const float* __restrict__ gt, const float* __restrict__ Mod,
            const float* __restrict__ Dem, float* __restrict__ out) {
    extern __shared__ __align__(16) char smem_raw[];
    const int tid = threadIdx.x, bid = blockIdx.x;

    // ======== phase A: transpose SoA + MUFU tables + fp64 col-sum partials ========
    {
        const int idx = bid * 1024 + tid;
        if (idx < 30000) {
            g_modT[idx % 3][idx / 3] = Mod[idx];
        } else if (idx < 60000) {
            int i2 = idx - 30000;
            g_demT[i2 % 3][i2 / 3] = Dem[i2];
        } else if (idx < 80000) {
            int q = idx - 60000;
            int p = q % 10000;
            int x = p / 100, y = p % 100;
            float s, c;
            if (q < 10000) {                       // M = W_100^{-xy}
                int r = (x * y) % 100;
                if (r > 50) r -= 100;              // exact reduction to [-pi, pi]
                __sincosf((float)(-TWOPI / 100.0) * (float)r, &s, &c);
                g_Mre[p] = c; g_Mim[p] = s;
            } else {                               // TW = W_10000^{-xy}
                int r = x * y;                     // < 10000
                if (r > 5000) r -= 10000;
                __sincosf((float)(-TWOPI / 10000.0) * (float)r, &s, &c);
                g_TWre[p] = c; g_TWim[p] = s;
            }
        }
        if (bid >= 118) {                          // 30 blocks: 6 cols x 5 chunks (fp64)
            const int b = bid - 118;
            const int col = b / 5, chunk = b % 5;
            const int k = col % 3;
            const float* src = (col < 3) ? Mod : Dem;
            const int base = chunk * 2000;
            double s = 0.0;
            for (int i = tid; i < 2000; i += 1024) s += (double)src[(base + i) * 3 + k];
            double* sh = reinterpret_cast<double*>(smem_raw);
            sh[tid] = s; __syncthreads();
            for (int o = 512; o; o >>= 1) {
                if (tid < o) sh[tid] += sh[tid + o];
                __syncthreads();
            }
            if (tid == 0) g_s6[col][chunk] = sh[0];
        }
    }
    grid_sync();   // 1

    // ======== phase B1: fwd stage 1 — S[b][c] = sum_a src[100a+b]·M[a][c], then ·TW ========
    if (bid < 60) {
        const int t = bid / 10, c0 = (bid % 10) * 10;
        const float* src = (t < 3) ? g_modT[t] : g_demT[t - 3];
        float* sG   = reinterpret_cast<float*>(smem_raw);      // [10000]
        float* sMre = sG + 10000;                              // [100][10]
        float* sMim = sMre + 1000;
        for (int i = tid; i < 10000; i += 1024) sG[i] = src[i];
        if (tid < 1000) {
            int a = tid / 10, cc = tid % 10;
            sMre[tid] = g_Mre[a * 100 + c0 + cc];
            sMim[tid] = g_Mim[a * 100 + c0 + cc];
        }
        __syncthreads();
        if (tid < 1000) {
            const int b = tid / 10, cc = tid % 10;
            float sre = 0.f, sim = 0.f;
#pragma unroll 5
            for (int a = 0; a < 100; a++) {
                float g = sG[a * 100 + b];
                sre = fmaf(g, sMre[a * 10 + cc], sre);
                sim = fmaf(g, sMim[a * 10 + cc], sim);
            }
            const int c = c0 + cc;
            float twre = g_TWre[b * 100 + c], twim = g_TWim[b * 100 + c];
            g_T[t][0][b * 100 + c] = sre * twre - sim * twim;
            g_T[t][1][b * 100 + c] = fmaf(sre, twim, sim * twre);
        }
    }
    grid_sync();   // 2

    // ======== phase B2: fwd stage 2 — F[c][d] = sum_b T[b][c]·M[b][d] ========
    if (bid < 60) {
        const int t = bid / 10, d0 = (bid % 10) * 10;
        float* sTre = reinterpret_cast<float*>(smem_raw);      // [25][100] chunk
        float* sTim = sTre + 2500;
        float* sMre = sTim + 2500;                             // [100][10]
        float* sMim = sMre + 1000;
        if (tid < 1000) {
            int b = tid / 10, dd = tid % 10;
            sMre[tid] = g_Mre[b * 100 + d0 + dd];
            sMim[tid] = g_Mim[b * 100 + d0 + dd];
        }
        float xre = 0.f, xim = 0.f;
        const int c = tid / 10, dd = tid % 10;
        for (int chunk = 0; chunk < 4; chunk++) {
            __syncthreads();
            for (int i = tid; i < 2500; i += 1024) {
                int bl = i / 100, c2 = i % 100;
                sTre[i] = g_T[t][0][(chunk * 25 + bl) * 100 + c2];
                sTim[i] = g_T[t][1][(chunk * 25 + bl) * 100 + c2];
            }
            __syncthreads();
            if (tid < 1000) {
#pragma unroll 5
                for (int bl = 0; bl < 25; bl++) {
                    int b = chunk * 25 + bl;
                    float tre = sTre[bl * 100 + c], tim = sTim[bl * 100 + c];
                    float mre = sMre[b * 10 + dd], mim = sMim[b * 10 + dd];
                    xre = fmaf(tre, mre, xre); xre = fmaf(-tim, mim, xre);
                    xim = fmaf(tre, mim, xim); xim = fmaf(tim, mre, xim);
                }
            }
        }
        if (tid < 1000) {
            g_F[t][0][c * 100 + d0 + dd] = xre;
            g_F[t][1][c * 100 + d0 + dd] = xim;
        }
    }
    grid_sync();   // 3

    // ======== phase B3: P = conj(Fm)·Fd ; U = P·conj(M) ; V = U·conj(TW) ========
    if (bid < 30) {
        const int j = bid / 10, c0 = (bid % 10) * 10;
        float* sPre = reinterpret_cast<float*>(smem_raw);      // [10][100]
        float* sPim = sPre + 1000;
        if (tid < 1000) {
            int cc = tid / 100, d = tid % 100;
            int ci = (c0 + cc) * 100 + d;
            float fmre = g_F[j][0][ci],     fmim = g_F[j][1][ci];
            float fdre = g_F[j + 3][0][ci], fdim = g_F[j + 3][1][ci];
            sPre[tid] = fmaf(fmre, fdre, fmim * fdim);         // conj(Fm)*Fd
            sPim[tid] = fmaf(fmre, fdim, -fmim * fdre);
        }
        __syncthreads();
        if (tid < 1000) {
            const int cc = tid / 100, g = tid % 100;
            float ure = 0.f, uim = 0.f;
#pragma unroll 4
            for (int d = 0; d < 100; d++) {
                float pre = sPre[cc * 100 + d], pim = sPim[cc * 100 + d];
                float mre = __ldg(&g_Mre[d * 100 + g]);
                float mim = __ldg(&g_Mim[d * 100 + g]);
                ure = fmaf(pre, mre, ure); ure = fmaf(pim, mim, ure);
                uim = fmaf(pim, mre, uim); uim = fmaf(-pre, mim, uim);
            }
            const int c = c0 + cc;
            float twre = g_TWre[c * 100 + g], twim = g_TWim[c * 100 + g];
            g_V[j][0][c * 100 + g] = fmaf(ure, twre, uim * twim);
            g_V[j][1][c * 100 + g] = fmaf(uim, twre, -ure * twim);
        }
    }
    grid_sync();   // 4

    // ======== phase B4: raw[g+100h] = 1e-4 * sum_c (Vre·Mre + Vim·Mim) + moments ========
    if (bid < 30) {
        const int j = bid / 10, g0 = (bid % 10) * 10;
        float* sVre = reinterpret_cast<float*>(smem_raw);      // [100][10]
        float* sVim = sVre + 1000;
        __shared__ double sm1[32], sm2[32];
        if (tid < 1000) {
            int c = tid / 10, gg = tid % 10;
            sVre[tid] = g_V[j][0][c * 100 + g0 + gg];
            sVim[tid] = g_V[j][1][c * 100 + g0 + gg];
        }
        __syncthreads();
        double ms = 0.0, ms2 = 0.0;
        if (tid < 1000) {
            const int gg = tid / 100, h = tid % 100;
            float acc = 0.f;
#pragma unroll 4
            for (int c = 0; c < 100; c++) {
                float vre = sVre[c * 10 + gg], vim = sVim[c * 10 + gg];
                acc = fmaf(vre, __ldg(&g_Mre[c * 100 + h]), acc);
                acc = fmaf(vim, __ldg(&g_Mim[c * 100 + h]), acc);
            }
            float raw = acc * 1e-4f;
            g_raw[j][(g0 + gg) + 100 * h] = raw;
            ms = (double)raw; ms2 = ms * ms;
        }
#pragma unroll
        for (int o = 16; o; o >>= 1) {
            ms  += __shfl_xor_sync(0xffffffffu, ms,  o);
            ms2 += __shfl_xor_sync(0xffffffffu, ms2, o);
        }
        if ((tid & 31) == 0) { sm1[tid >> 5] = ms; sm2[tid >> 5] = ms2; }
        __syncthreads();
        if (tid < 32) {
            double s  = sm1[tid], sq = sm2[tid];
#pragma unroll
            for (int o = 16; o; o >>= 1) {
                s  += __shfl_xor_sync(0xffffffffu, s,  o);
                sq += __shfl_xor_sync(0xffffffffu, sq, o);
            }
            if (tid == 0) { g_bs1[j][bid % 10] = s; g_bs2[j][bid % 10] = sq; }
        }
    }
    grid_sync();   // 5

    // ======== phase D: every block folds stats redundantly ========
    __shared__ float sh_scale[3], sh_mean[3], sh_amb[3];
    __shared__ double sh_sums6[6];
    {
        const int w = tid >> 5, lane = tid & 31;
        if (w < 6) {
            double s = (lane < 5) ? g_s6[w][lane] : 0.0;
#pragma unroll
            for (int o = 16; o; o >>= 1) s += __shfl_xor_sync(0xffffffffu, s, o);
            if (lane == 0) sh_sums6[w] = s;
        }
        __syncthreads();
        if (w < 3) {
            double s1 = (lane < 10) ? g_bs1[w][lane] : 0.0;
            double s2 = (lane < 10) ? g_bs2[w][lane] : 0.0;
#pragma unroll
            for (int o = 16; o; o >>= 1) {
                s1 += __shfl_xor_sync(0xffffffffu, s1, o);
                s2 += __shfl_xor_sync(0xffffffffu, s2, o);
            }
            if (lane == 0) {
                double mean = s1 / NCORR;
                double var  = (s2 - s1 * s1 / NCORR) / (NCORR - 1);
                double sgn  = (sh_sums6[w] < 0.0) ? -1.0 : 1.0;
                sh_scale[w] = (float)(sgn * LOG2E / sqrt(var));
                sh_mean[w]  = (float)mean;
            }
        }
        if (tid >= 96 && tid < 99) sh_amb[tid - 96] = (float)(1.0e6 * sh_sums6[3 + (tid - 96)]);
    }
    __syncthreads();

    // ======== phase E: build SoA templates (u, v) into smem ========
    float* s_u = reinterpret_cast<float*>(smem_raw);
    float* s_v = s_u + 10048;
    {
        const float sc0 = sh_scale[0], sc1 = sh_scale[1], sc2 = sh_scale[2];
        const float mv0 = sh_mean[0],  mv1 = sh_mean[1],  mv2 = sh_mean[2];
        for (int n = tid; n < NCORR; n += 1024) {
            float c0 = sc0 * (g_raw[0][n] - mv0);
            float c1 = sc1 * (g_raw[1][n] - mv1);
            float c2 = sc2 * (g_raw[2][n] - mv2);
            s_u[n] = (c0 - c1) * RSQRT2;
            s_v[n] = (c0 + c1 - 2.f * c2) * RSQRT6;
        }
    }
    __syncthreads();

    // ======== phase F: theta-grid decode — exactly 1 task per warp ========
    {
        const int lane = tid & 31;
        const int task = bid * 32 + (tid >> 5);
        const int j = task >> 2, chunk = task & 3;
        const int base = chunk * 2500;
        float sn_, cs_;
        sincosf((float)((double)j * (TWOPI / MTHETA)), &sn_, &cs_);
        const float p = SQRT2F * cs_, q = SQRT2F * sn_;
        const ull pp = pk(p, p), qq = pk(q, q);
        const ull c128 = pk(128.f, 128.f);

        ull sA = 0ull, sB = 0ull, wA = 0ull, wB = 0ull;
        const int nb = base + 4 * lane;
        ull nfA = pk((float)nb, (float)(nb + 1));
        ull nfB = pk((float)(nb + 2), (float)(nb + 3));
        const ulonglong2* pu = reinterpret_cast<const ulonglong2*>(&s_u[nb]);
        const ulonglong2* pv = reinterpret_cast<const ulonglong2*>(&s_v[nb]);

#pragma unroll 4
        for (int it = 0; it < 19; it++) {         // 19*128 = 2432 of 2500
            ulonglong2 U = pu[it * 32];
            ulonglong2 V = pv[it * 32];
            ull zA = f2fma(pp, U.x, f2mul(qq, V.x));
            ull zB = f2fma(pp, U.y, f2mul(qq, V.y));
            float a, b;
            upk(zA, a, b); ull eA = pk(ex2(a), ex2(b));
            upk(zB, a, b); ull eB = pk(ex2(a), ex2(b));
            sA = f2add(sA, eA);  sB = f2add(sB, eB);
            wA = f2fma(eA, nfA, wA); wB = f2fma(eB, nfB, wB);
            nfA = f2add(nfA, c128);  nfB = f2add(nfB, c128);
        }
        if (lane < 17) {                          // tail: 68 samples
            const int n = base + 2432 + 4 * lane;
            ulonglong2 U = *reinterpret_cast<const ulonglong2*>(&s_u[n]);
            ulonglong2 V = *reinterpret_cast<const ulonglong2*>(&s_v[n]);
            ull ntA = pk((float)n, (float)(n + 1));
            ull ntB = pk((float)(n + 2), (float)(n + 3));
            ull zA = f2fma(pp, U.x, f2mul(qq, V.x));
            ull zB = f2fma(pp, U.y, f2mul(qq, V.y));
            float a, b;
            upk(zA, a, b); ull eA = pk(ex2(a), ex2(b));
            upk(zB, a, b); ull eB = pk(ex2(a), ex2(b));
            sA = f2add(sA, eA);  sB = f2add(sB, eB);
            wA = f2fma(eA, ntA, wA); wB = f2fma(eB, ntB, wB);
        }
        float a, b, s, w;
        ull st = f2add(sA, sB), wt = f2add(wA, wB);
        upk(st, a, b); s = a + b;
        upk(wt, a, b); w = a + b;
#pragma unroll
        for (int o = 16; o; o >>= 1) {
            s += __shfl_xor_sync(0xffffffffu, s, o);
            w += __shfl_xor_sync(0xffffffffu, w, o);
        }
        if (lane == 0) g_ps[j][chunk] = make_float2(s, w);
    }
    grid_sync();   // 6

    // ======== phase G: gather per pixel (atan2 + lerp) ========
    {
        const float amb0 = sh_amb[0], amb1 = sh_amb[1], amb2 = sh_amb[2];
        const float inv_dt = (float)(MTHETA / TWOPI);
        const int px = bid * 1024 + tid;
        if (px < NPIX) {
            int idx = (int)rintf(gt[px]);
            idx = min(max(idx, 0), NCORR - 1);
            float x = __ldcg(&g_raw[0][idx]) + amb0;
            float y = __ldcg(&g_raw[1][idx]) + amb1;
            float z = __ldcg(&g_raw[2][idx]) + amb2;
            float pv = (x - y);
            float qv = (x + y - 2.f * z) * (RSQRT6 / RSQRT2);
            float th = atan2f(qv, pv);
            if (th < 0.f) th += (float)TWOPI;
            float g = th * inv_dt;
            int j0 = (int)g;
            float f = g - (float)j0;
            if (j0 >= MTHETA) j0 -= MTHETA;
            int j1 = j0 + 1; if (j1 >= MTHETA) j1 -= MTHETA;
            const float4* q0 = reinterpret_cast<const float4*>(&g_ps[j0][0]);
            const float4* q1 = reinterpret_cast<const float4*>(&g_ps[j1][0]);
            float4 u0 = __ldcg(&q0[0]), u1 = __ldcg(&q0[1]);
            float4 v0 = __ldcg(&q1[0]), v1 = __ldcg(&q1[1]);
            float S0 = u0.x + u0.z + u1.x + u1.z;
            float W0 = u0.y + u0.w + u1.y + u1.w;
            float S1 = v0.x + v0.z + v1.x + v1.z;
            float W1 = v0.y + v0.w + v1.y + v1.w;
            float F0 = W0 / S0, F1 = W1 / S1;
            out[px] = fmaf(f, F1 - F0, F0);
        }
    }
}

extern "C" void kernel_launch(void* const* d_in, const int* in_sizes, int n_in,
                              void* d_out, int out_size) {
    const float* gt  = (const float*)d_in[0];
    const float* Mod = (const float*)d_in[1];
    const float* Dem = (const float*)d_in[2];
    float* out = (float*)d_out;

    int smem = 98304;   // max phase use ~80.4KB (templates); 148 blocks -> 1/SM, all resident
    cudaFuncSetAttribute(mega_kernel, cudaFuncAttributeMaxDynamicSharedMemorySize, smem);
    mega_kernel<<<NBLK, 1024, smem>>>(gt, Mod, Dem, out);
}

// round 11
// speedup vs baseline: 1.2798x; 1.2792x over previous
#include <cuda_runtime.h>
#include <cuda_bf16.h>
#include <stdint.h>

#define NCORR    10000
#define MPAD     10048                 // 157*64
#define DEM_LEN  20480
#define NCHUNK_M 157
#define CHUNK_M  64
#define NPAD     10240
#define NTILES   (10 * 3 * NCHUNK_M)   // 4710
#define NPIX     16384
#define MTHETA   1184                  // θ-grid; ×4 n-chunks = 4736 tasks = #warps
#define NBLK     148
#define LOG2E    1.4426950408889634
#define RSQRT2   0.70710678118654752f
#define RSQRT6   0.40824829046386302f
#define SQRT2F   1.41421356237309505f
#define TWOPI    6.283185307179586476925286766559

typedef unsigned long long ull;

__device__ __forceinline__ ull pk(float lo, float hi) {
    ull r; asm("mov.b64 %0, {%1,%2};" : "=l"(r) : "f"(lo), "f"(hi)); return r;
}
__device__ __forceinline__ void upk(ull v, float& lo, float& hi) {
    asm("mov.b64 {%0,%1}, %2;" : "=f"(lo), "=f"(hi) : "l"(v));
}
__device__ __forceinline__ ull f2mul(ull a, ull b) {
    ull d; asm("mul.rn.f32x2 %0, %1, %2;" : "=l"(d) : "l"(a), "l"(b)); return d;
}
__device__ __forceinline__ ull f2add(ull a, ull b) {
    ull d; asm("add.rn.f32x2 %0, %1, %2;" : "=l"(d) : "l"(a), "l"(b)); return d;
}
__device__ __forceinline__ ull f2fma(ull a, ull b, ull c) {
    ull d; asm("fma.rn.f32x2 %0, %1, %2, %3;" : "=l"(d) : "l"(a), "l"(b), "l"(c)); return d;
}
__device__ __forceinline__ float ex2(float x) {
    float r; asm("ex2.approx.f32 %0, %1;" : "=f"(r) : "f"(x)); return r;
}

// ---------------- device scratch ----------------
__device__ float  g_modT[3][MPAD];
__device__ float  g_demT2[3][DEM_LEN];
__device__ float  g_part[3][NCHUNK_M][NPAD];
__device__ float  g_raw[3][NCORR];
__device__ double g_s6[6][5];                    // column-sum partials (30 blocks)
__device__ double g_bs1[3][40], g_bs2[3][40];    // corr moment partials
__device__ __align__(16) float2 g_ps[MTHETA][4]; // per-(theta, n-chunk) partial (S, W)
__device__ int    g_tilectr;                     // corr tile counter (reset each launch)
__device__ int    g_sync;                        // monotonic ticket barrier (never reset)

// Monotonic-ticket grid barrier: replay-safe (no reset). All 148 blocks resident.
__device__ __forceinline__ void grid_sync() {
    __syncthreads();
    if (threadIdx.x == 0) {
        __threadfence();
        int t = atomicAdd(&g_sync, 1);
        int target = (t / NBLK + 1) * NBLK;
        while (*(volatile int*)&g_sync < target) {}
        __threadfence();
    }
    __syncthreads();
}

__global__ void __launch_bounds__(1024, 1)
mega_kernel(const float* __restrict__ gt, const float* __restrict__ Mod,
            const float* __restrict__ Dem, float* __restrict__ out) {
    extern __shared__ __align__(16) char smem_raw[];
    const int tid = threadIdx.x, bid = blockIdx.x;

    // ======== phase A: transpose+dup+pad + fp64 col-sum partials + counter reset ========
    {
        const int idx = bid * 1024 + tid;
        if (idx == 0) g_tilectr = 0;
        if (idx < 3 * DEM_LEN) {
            const int k = idx / DEM_LEN, j = idx % DEM_LEN;
            if (j < NCORR) {
                g_modT[k][j] = Mod[j * 3 + k];
                float d = Dem[j * 3 + k];
                g_demT2[k][j]         = d;
                g_demT2[k][j + NCORR] = d;
            } else {
                if (j < MPAD)       g_modT[k][j]  = 0.f;
                if (j >= 2 * NCORR) g_demT2[k][j] = 0.f;
            }
        }
        if (bid >= 118) {                          // 30 blocks: 6 cols x 5 chunks (fp64)
            const int b = bid - 118;
            const int col = b / 5, chunk = b % 5;
            const int k = col % 3;
            const float* src = (col < 3) ? Mod : Dem;
            const int base = chunk * 2000;
            double s = 0.0;
            for (int i = tid; i < 2000; i += 1024) s += (double)src[(base + i) * 3 + k];
            double* sh = reinterpret_cast<double*>(smem_raw);
            sh[tid] = s; __syncthreads();
            for (int o = 512; o; o >>= 1) {
                if (tid < o) sh[tid] += sh[tid + o];
                __syncthreads();
            }
            if (tid == 0) g_s6[col][chunk] = sh[0];
        }
    }
    grid_sync();   // 1

    // ======== phase B: correlation — 8 sub-blocks x 128 thr, double-buffered stealing ========
    // tile = (n-slice 1024, k, m-chunk 64); 1 named barrier per tile; next tile's
    // index + data prefetched during compute.
    {
        float* sdem_all = reinterpret_cast<float*>(smem_raw);              // 8*2*1120 floats
        ull*   smod_all = reinterpret_cast<ull*>(smem_raw + 8 * 2 * 1120 * 4);
        __shared__ int s_tile[8][2];
        const int sub = tid >> 7, stid = tid & 127;
        float* sdem0 = sdem_all + (sub * 2 + 0) * 1120;
        float* sdem1 = sdem_all + (sub * 2 + 1) * 1120;
        ull*   smod0 = smod_all + (sub * 2 + 0) * 64;
        ull*   smod1 = smod_all + (sub * 2 + 1) * 64;

        // prologue: fetch tile0 index, load it, prefetch tile1 index
        if (stid == 0) s_tile[sub][0] = atomicAdd(&g_tilectr, 1);
        asm volatile("bar.sync %0, 128;" :: "r"(sub + 1) : "memory");
        int tile = s_tile[sub][0];
        if (stid == 0) s_tile[sub][1] = atomicAdd(&g_tilectr, 1);
        if (tile < NTILES) {
            const int nslice = tile % 10, rem = tile / 10;
            const int k = rem % 3, mc = rem / 3;
            const int n0 = nslice * 1024, m0 = mc * CHUNK_M;
            if (stid < CHUNK_M) { float v = g_modT[k][m0 + stid]; smod0[stid] = pk(v, v); }
            for (int i = stid; i < 1104; i += 128) sdem0[i] = g_demT2[k][m0 + n0 + i];
        }
        asm volatile("bar.sync %0, 128;" :: "r"(sub + 1) : "memory");

        int cur = 0;
        while (tile < NTILES) {
            const int nxt = s_tile[sub][cur ^ 1];
            float* sdemN = cur ? sdem0 : sdem1;        // buffer being filled (cur^1)
            ull*   smodN = cur ? smod0 : smod1;
            float* sdemC = cur ? sdem1 : sdem0;        // buffer being computed (cur)
            ull*   smodC = cur ? smod1 : smod0;
            if (nxt < NTILES) {
                if (stid == 0) s_tile[sub][cur] = atomicAdd(&g_tilectr, 1);
                const int nslice = nxt % 10, rem = nxt / 10;
                const int k2 = rem % 3, mc2 = rem / 3;
                const int n0b = nslice * 1024, m0b = mc2 * CHUNK_M;
                if (stid < CHUNK_M) { float v = g_modT[k2][m0b + stid]; smodN[stid] = pk(v, v); }
                for (int i = stid; i < 1104; i += 128) sdemN[i] = g_demT2[k2][m0b + n0b + i];
            }
            // compute current tile (overlaps the prefetch LDGs above)
            {
                const int nslice = tile % 10, rem = tile / 10;
                const int k = rem % 3, mc = rem / 3;
                const int n0 = nslice * 1024;
                ull a0 = 0ull, a1 = 0ull, a2 = 0ull, a3 = 0ull;
                const ulonglong2* qp = reinterpret_cast<const ulonglong2*>(&sdemC[8 * stid]);
                ulonglong2 qa = qp[0], qb = qp[1], qc = qp[2];
                ull P0 = qa.x, P1 = qa.y, P2 = qb.x, P3 = qb.y, P4 = qc.x, P5 = qc.y;
#pragma unroll 4
                for (int g = 0; g < 16; g++) {        // 16 groups x 4 m = 64 m
                    ull mv0 = smodC[4 * g], mv1 = smodC[4 * g + 1],
                        mv2 = smodC[4 * g + 2], mv3 = smodC[4 * g + 3];
                    float w0, w1, w2, w3, w4, w5, w6, w7, w8, w9, w10, w11;
                    upk(P0, w0, w1); upk(P1, w2, w3); upk(P2, w4, w5);
                    upk(P3, w6, w7); upk(P4, w8, w9); upk(P5, w10, w11);
                    ull B0 = pk(w1, w2), B1 = pk(w3, w4), B2 = pk(w5, w6),
                        B3 = pk(w7, w8), B4 = pk(w9, w10);
                    a0 = f2fma(mv0, P0, a0); a1 = f2fma(mv0, P1, a1);
                    a2 = f2fma(mv0, P2, a2); a3 = f2fma(mv0, P3, a3);
                    a0 = f2fma(mv1, B0, a0); a1 = f2fma(mv1, B1, a1);
                    a2 = f2fma(mv1, B2, a2); a3 = f2fma(mv1, B3, a3);
                    a0 = f2fma(mv2, P1, a0); a1 = f2fma(mv2, P2, a1);
                    a2 = f2fma(mv2, P3, a2); a3 = f2fma(mv2, P4, a3);
                    a0 = f2fma(mv3, B1, a0); a1 = f2fma(mv3, B2, a1);
                    a2 = f2fma(mv3, B3, a2); a3 = f2fma(mv3, B4, a3);
                    P0 = P2; P1 = P3; P2 = P4; P3 = P5;
                    ulonglong2 qn = qp[g + 3];
                    P4 = qn.x; P5 = qn.y;
                }
                float o0, o1, o2, o3, o4, o5, o6, o7;
                upk(a0, o0, o1); upk(a1, o2, o3); upk(a2, o4, o5); upk(a3, o6, o7);
                float* dst = &g_part[k][mc][n0 + 8 * stid];
                *reinterpret_cast<float4*>(dst)     = make_float4(o0, o1, o2, o3);
                *reinterpret_cast<float4*>(dst + 4) = make_float4(o4, o5, o6, o7);
            }
            asm volatile("bar.sync %0, 128;" :: "r"(sub + 1) : "memory");
            tile = nxt; cur ^= 1;
        }
    }
    grid_sync();   // 2

    // ======== phase C: fold m-chunk partials (blocks 0..119) + fp64 moments ========
    if (bid < 120) {
        float* comb = reinterpret_cast<float*>(smem_raw);     // [4][256]
        __shared__ double sm1[8], sm2[8];
        const int k = bid / 40, rem = bid % 40;
        const int n0 = rem * 256;
        const int r = tid >> 8, j = tid & 255;
        const int n = n0 + j;
        {
            float acc = 0.f;
            const int c0 = r * 40, cend = (r < 3) ? c0 + 40 : NCHUNK_M;
            for (int c = c0; c < cend; c++) acc += g_part[k][c][n];
            comb[r * 256 + j] = acc;
        }
        __syncthreads();
        if (tid < 256) {
            float acc = comb[tid] + comb[256 + tid] + comb[512 + tid] + comb[768 + tid];
            double x = 0.0;
            if (n0 + tid < NCORR) { g_raw[k][n0 + tid] = acc; x = (double)acc; }
            double s = x, sq = x * x;
#pragma unroll
            for (int o = 16; o; o >>= 1) {
                s  += __shfl_xor_sync(0xffffffffu, s,  o);
                sq += __shfl_xor_sync(0xffffffffu, sq, o);
            }
            if ((tid & 31) == 0) { sm1[tid >> 5] = s; sm2[tid >> 5] = sq; }
        }
        __syncthreads();
        if (tid < 32) {
            double s  = (tid < 8) ? sm1[tid] : 0.0;
            double sq = (tid < 8) ? sm2[tid] : 0.0;
#pragma unroll
            for (int o = 16; o; o >>= 1) {
                s  += __shfl_xor_sync(0xffffffffu, s,  o);
                sq += __shfl_xor_sync(0xffffffffu, sq, o);
            }
            if (tid == 0) { g_bs1[k][rem] = s; g_bs2[k][rem] = sq; }
        }
    }
    grid_sync();   // 3

    // ======== phase D: every block folds stats redundantly ========
    __shared__ float sh_scale[3], sh_mean[3], sh_amb[3];
    __shared__ double sh_sums6[6];
    {
        const int w = tid >> 5, lane = tid & 31;
        if (w < 6) {
            double s = (lane < 5) ? g_s6[w][lane] : 0.0;
#pragma unroll
            for (int o = 16; o; o >>= 1) s += __shfl_xor_sync(0xffffffffu, s, o);
            if (lane == 0) sh_sums6[w] = s;
        }
        __syncthreads();
        if (w < 3) {
            double s1 = g_bs1[w][lane] + ((lane < 8) ? g_bs1[w][lane + 32] : 0.0);
            double s2 = g_bs2[w][lane] + ((lane < 8) ? g_bs2[w][lane + 32] : 0.0);
#pragma unroll
            for (int o = 16; o; o >>= 1) {
                s1 += __shfl_xor_sync(0xffffffffu, s1, o);
                s2 += __shfl_xor_sync(0xffffffffu, s2, o);
            }
            if (lane == 0) {
                double mean = s1 / NCORR;
                double var  = (s2 - s1 * s1 / NCORR) / (NCORR - 1);
                double sgn  = (sh_sums6[w] < 0.0) ? -1.0 : 1.0;
                sh_scale[w] = (float)(sgn * LOG2E / sqrt(var));
                sh_mean[w]  = (float)mean;
            }
        }
        if (tid >= 96 && tid < 99) sh_amb[tid - 96] = (float)(1.0e6 * sh_sums6[3 + (tid - 96)]);
    }
    __syncthreads();

    // ======== phase E: build SoA templates (u, v) into smem ========
    float* s_u = reinterpret_cast<float*>(smem_raw);
    float* s_v = s_u + 10048;
    {
        const float sc0 = sh_scale[0], sc1 = sh_scale[1], sc2 = sh_scale[2];
        const float mv0 = sh_mean[0],  mv1 = sh_mean[1],  mv2 = sh_mean[2];
        for (int n = tid; n < NCORR; n += 1024) {
            float c0 = sc0 * (g_raw[0][n] - mv0);
            float c1 = sc1 * (g_raw[1][n] - mv1);
            float c2 = sc2 * (g_raw[2][n] - mv2);
            s_u[n] = (c0 - c1) * RSQRT2;
            s_v[n] = (c0 + c1 - 2.f * c2) * RSQRT6;
        }
    }
    __syncthreads();

    // ======== phase F: theta-grid decode — exactly 1 task per warp ========
    {
        const int lane = tid & 31;
        const int task = bid * 32 + (tid >> 5);
        const int j = task >> 2, chunk = task & 3;
        const int base = chunk * 2500;
        float sn_, cs_;
        sincosf((float)((double)j * (TWOPI / MTHETA)), &sn_, &cs_);
        const float p = SQRT2F * cs_, q = SQRT2F * sn_;
        const ull pp = pk(p, p), qq = pk(q, q);
        const ull c128 = pk(128.f, 128.f);

        ull sA = 0ull, sB = 0ull, wA = 0ull, wB = 0ull;
        const int nb = base + 4 * lane;
        ull nfA = pk((float)nb, (float)(nb + 1));
        ull nfB = pk((float)(nb + 2), (float)(nb + 3));
        const ulonglong2* pu = reinterpret_cast<const ulonglong2*>(&s_u[nb]);
        const ulonglong2* pv = reinterpret_cast<const ulonglong2*>(&s_v[nb]);

#pragma unroll 4
        for (int it = 0; it < 19; it++) {         // 19*128 = 2432 of 2500
            ulonglong2 U = pu[it * 32];
            ulonglong2 V = pv[it * 32];
            ull zA = f2fma(pp, U.x, f2mul(qq, V.x));
            ull zB = f2fma(pp, U.y, f2mul(qq, V.y));
            float a, b;
            upk(zA, a, b); ull eA = pk(ex2(a), ex2(b));
            upk(zB, a, b); ull eB = pk(ex2(a), ex2(b));
            sA = f2add(sA, eA);  sB = f2add(sB, eB);
            wA = f2fma(eA, nfA, wA); wB = f2fma(eB, nfB, wB);
            nfA = f2add(nfA, c128);  nfB = f2add(nfB, c128);
        }
        if (lane < 17) {                          // tail: 68 samples
            const int n = base + 2432 + 4 * lane;
            ulonglong2 U = *reinterpret_cast<const ulonglong2*>(&s_u[n]);
            ulonglong2 V = *reinterpret_cast<const ulonglong2*>(&s_v[n]);
            ull ntA = pk((float)n, (float)(n + 1));
            ull ntB = pk((float)(n + 2), (float)(n + 3));
            ull zA = f2fma(pp, U.x, f2mul(qq, V.x));
            ull zB = f2fma(pp, U.y, f2mul(qq, V.y));
            float a, b;
            upk(zA, a, b); ull eA = pk(ex2(a), ex2(b));
            upk(zB, a, b); ull eB = pk(ex2(a), ex2(b));
            sA = f2add(sA, eA);  sB = f2add(sB, eB);
            wA = f2fma(eA, ntA, wA); wB = f2fma(eB, ntB, wB);
        }
        float a, b, s, w;
        ull st = f2add(sA, sB), wt = f2add(wA, wB);
        upk(st, a, b); s = a + b;
        upk(wt, a, b); w = a + b;
#pragma unroll
        for (int o = 16; o; o >>= 1) {
            s += __shfl_xor_sync(0xffffffffu, s, o);
            w += __shfl_xor_sync(0xffffffffu, w, o);
        }
        if (lane == 0) g_ps[j][chunk] = make_float2(s, w);
    }
    grid_sync();   // 4

    // ======== phase G: gather per pixel (atan2 + lerp) ========
    {
        const float amb0 = sh_amb[0], amb1 = sh_amb[1], amb2 = sh_amb[2];
        const float inv_dt = (float)(MTHETA / TWOPI);
        const int px = bid * 1024 + tid;
        if (px < NPIX) {
            int idx = (int)rintf(gt[px]);
            idx = min(max(idx, 0), NCORR - 1);
            float x = __ldcg(&g_raw[0][idx]) + amb0;
            float y = __ldcg(&g_raw[1][idx]) + amb1;
            float z = __ldcg(&g_raw[2][idx]) + amb2;
            float pv = (x - y);
            float qv = (x + y - 2.f * z) * (RSQRT6 / RSQRT2);
            float th = atan2f(qv, pv);
            if (th < 0.f) th += (float)TWOPI;
            float g = th * inv_dt;
            int j0 = (int)g;
            float f = g - (float)j0;
            if (j0 >= MTHETA) j0 -= MTHETA;
            int j1 = j0 + 1; if (j1 >= MTHETA) j1 -= MTHETA;
            const float4* q0 = reinterpret_cast<const float4*>(&g_ps[j0][0]);
            const float4* q1 = reinterpret_cast<const float4*>(&g_ps[j1][0]);
            float4 u0 = __ldcg(&q0[0]), u1 = __ldcg(&q0[1]);
            float4 v0 = __ldcg(&q1[0]), v1 = __ldcg(&q1[1]);
            float S0 = u0.x + u0.z + u1.x + u1.z;
            float W0 = u0.y + u0.w + u1.y + u1.w;
            float S1 = v0.x + v0.z + v1.x + v1.z;
            float W1 = v0.y + v0.w + v1.y + v1.w;
            float F0 = W0 / S0, F1 = W1 / S1;
            out[px] = fmaf(f, F1 - F0, F0);
        }
    }
}

extern "C" void kernel_launch(void* const* d_in, const int* in_sizes, int n_in,
                              void* d_out, int out_size) {
    const float* gt  = (const float*)d_in[0];
    const float* Mod = (const float*)d_in[1];
    const float* Dem = (const float*)d_in[2];
    float* out = (float*)d_out;

    int smem = 98304;   // corr double-buffer ~80KB, templates 80.4KB; 148 blocks -> 1/SM
    cudaFuncSetAttribute(mega_kernel, cudaFuncAttributeMaxDynamicSharedMemorySize, smem);
    mega_kernel<<<NBLK, 1024, smem>>>(gt, Mod, Dem, out);
}

// round 13
// speedup vs baseline: 1.4249x; 1.1134x over previous
#include <cuda_runtime.h>
#include <cuda_bf16.h>
#include <stdint.h>

#define NCORR    10000
#define MPAD     10048                 // 157*64
#define DEM_LEN  20480
#define NCHUNK_M 157
#define CHUNK_M  64
#define NPAD     10240
#define NTILES   (10 * 3 * NCHUNK_M)   // 4710
#define NPIX     16384
#define MTHETA   1184                  // θ-grid; ×4 n-chunks = 4736 tasks = #warps
#define NBLK     148
#define LOG2E    1.4426950408889634
#define RSQRT2   0.70710678118654752f
#define RSQRT6   0.40824829046386302f
#define SQRT2F   1.41421356237309505f
#define TWOPI    6.283185307179586476925286766559

typedef unsigned long long ull;

__device__ __forceinline__ ull pk(float lo, float hi) {
    ull r; asm("mov.b64 %0, {%1,%2};" : "=l"(r) : "f"(lo), "f"(hi)); return r;
}
__device__ __forceinline__ void upk(ull v, float& lo, float& hi) {
    asm("mov.b64 {%0,%1}, %2;" : "=f"(lo), "=f"(hi) : "l"(v));
}
__device__ __forceinline__ ull f2mul(ull a, ull b) {
    ull d; asm("mul.rn.f32x2 %0, %1, %2;" : "=l"(d) : "l"(a), "l"(b)); return d;
}
__device__ __forceinline__ ull f2add(ull a, ull b) {
    ull d; asm("add.rn.f32x2 %0, %1, %2;" : "=l"(d) : "l"(a), "l"(b)); return d;
}
__device__ __forceinline__ ull f2fma(ull a, ull b, ull c) {
    ull d; asm("fma.rn.f32x2 %0, %1, %2, %3;" : "=l"(d) : "l"(a), "l"(b), "l"(c)); return d;
}
__device__ __forceinline__ float ex2(float x) {
    float r; asm("ex2.approx.f32 %0, %1;" : "=f"(r) : "f"(x)); return r;
}

// ---------------- device scratch ----------------
__device__ float  g_modT[3][MPAD];
__device__ float  g_demT2[3][DEM_LEN];
__device__ float  g_part[3][NCHUNK_M][NPAD];
__device__ float  g_raw[3][NCORR];
__device__ double g_s6[6][5];                    // column-sum partials
__device__ double g_bs1[3][40], g_bs2[3][40];    // corr moment partials
__device__ __align__(16) float2 g_ps[MTHETA][4]; // per-(theta, n-chunk) partial (S, W)
__device__ int    g_tilectr;                     // corr tile counter (reset each launch)
__device__ int    g_sync;                        // monotonic ticket barrier (never reset)

// Monotonic-ticket grid barrier (used only inside tail_kernel, 148 resident blocks).
__device__ __forceinline__ void grid_sync() {
    __syncthreads();
    if (threadIdx.x == 0) {
        __threadfence();
        int t = atomicAdd(&g_sync, 1);
        int target = (t / NBLK + 1) * NBLK;
        while (*(volatile int*)&g_sync < target) {}
        __threadfence();
    }
    __syncthreads();
}

// ======== kernel 1: prep (transpose+dup+pad) + fp64 col-sum partials ========
__global__ void __launch_bounds__(1024) prep_kernel(const float* __restrict__ Mod,
                                                    const float* __restrict__ Dem) {
    const int tid = threadIdx.x, bid = blockIdx.x;
    if (bid < 60) {                               // 60*1024 = 61440 = 3*DEM_LEN
        const int idx = bid * 1024 + tid;
        if (idx == 0) g_tilectr = 0;
        const int k = idx / DEM_LEN, j = idx % DEM_LEN;
        if (j < NCORR) {
            g_modT[k][j] = Mod[j * 3 + k];
            float d = Dem[j * 3 + k];
            g_demT2[k][j]         = d;
            g_demT2[k][j + NCORR] = d;
        } else {
            if (j < MPAD)       g_modT[k][j]  = 0.f;
            if (j >= 2 * NCORR) g_demT2[k][j] = 0.f;
        }
    } else {                                      // 30 blocks: 6 cols x 5 chunks (fp64)
        __shared__ double sh[1024];
        const int b = bid - 60;
        const int col = b / 5, chunk = b % 5;
        const int k = col % 3;
        const float* src = (col < 3) ? Mod : Dem;
        const int base = chunk * 2000;
        double s = 0.0;
        for (int i = tid; i < 2000; i += 1024) s += (double)src[(base + i) * 3 + k];
        sh[tid] = s; __syncthreads();
        for (int o = 512; o; o >>= 1) {
            if (tid < o) sh[tid] += sh[tid + o];
            __syncthreads();
        }
        if (tid == 0) g_s6[col][chunk] = sh[0];
    }
}

// ======== kernel 2: correlation — 128-thr blocks, work-stealing, high occupancy ========
__global__ void __launch_bounds__(128) corr_kernel() {
    __shared__ __align__(16) float sdem[1120];
    __shared__ ull smod[64];
    __shared__ int s_tile;
    const int stid = threadIdx.x;
    while (true) {
        if (stid == 0) s_tile = atomicAdd(&g_tilectr, 1);
        __syncthreads();
        const int tile = s_tile;
        if (tile >= NTILES) break;
        const int nslice = tile % 10, rem = tile / 10;
        const int k = rem % 3, mc = rem / 3;
        const int n0 = nslice * 1024, m0 = mc * CHUNK_M;

        if (stid < CHUNK_M) { float v = g_modT[k][m0 + stid]; smod[stid] = pk(v, v); }
        for (int i = stid; i < 1104; i += 128) sdem[i] = g_demT2[k][m0 + n0 + i];
        __syncthreads();

        ull a0 = 0ull, a1 = 0ull, a2 = 0ull, a3 = 0ull;
        const ulonglong2* qp = reinterpret_cast<const ulonglong2*>(&sdem[8 * stid]);
        ulonglong2 qa = qp[0], qb = qp[1], qc = qp[2];
        ull P0 = qa.x, P1 = qa.y, P2 = qb.x, P3 = qb.y, P4 = qc.x, P5 = qc.y;
#pragma unroll 4
        for (int g = 0; g < 16; g++) {            // 16 groups x 4 m = 64 m
            ull mv0 = smod[4 * g], mv1 = smod[4 * g + 1],
                mv2 = smod[4 * g + 2], mv3 = smod[4 * g + 3];
            float w0, w1, w2, w3, w4, w5, w6, w7, w8, w9, w10, w11;
            upk(P0, w0, w1); upk(P1, w2, w3); upk(P2, w4, w5);
            upk(P3, w6, w7); upk(P4, w8, w9); upk(P5, w10, w11);
            ull B0 = pk(w1, w2), B1 = pk(w3, w4), B2 = pk(w5, w6),
                B3 = pk(w7, w8), B4 = pk(w9, w10);
            a0 = f2fma(mv0, P0, a0); a1 = f2fma(mv0, P1, a1);
            a2 = f2fma(mv0, P2, a2); a3 = f2fma(mv0, P3, a3);
            a0 = f2fma(mv1, B0, a0); a1 = f2fma(mv1, B1, a1);
            a2 = f2fma(mv1, B2, a2); a3 = f2fma(mv1, B3, a3);
            a0 = f2fma(mv2, P1, a0); a1 = f2fma(mv2, P2, a1);
            a2 = f2fma(mv2, P3, a2); a3 = f2fma(mv2, P4, a3);
            a0 = f2fma(mv3, B1, a0); a1 = f2fma(mv3, B2, a1);
            a2 = f2fma(mv3, B3, a2); a3 = f2fma(mv3, B4, a3);
            P0 = P2; P1 = P3; P2 = P4; P3 = P5;
            ulonglong2 qn = qp[g + 3];
            P4 = qn.x; P5 = qn.y;
        }
        {
            float o0, o1, o2, o3, o4, o5, o6, o7;
            upk(a0, o0, o1); upk(a1, o2, o3); upk(a2, o4, o5); upk(a3, o6, o7);
            float* dst = &g_part[k][mc][n0 + 8 * stid];
            *reinterpret_cast<float4*>(dst)     = make_float4(o0, o1, o2, o3);
            *reinterpret_cast<float4*>(dst + 4) = make_float4(o4, o5, o6, o7);
        }
        __syncthreads();
    }
}

// ======== kernel 3: reduce + stats + build + theta decode + gather ========
__global__ void __launch_bounds__(1024, 1)
tail_kernel(const float* __restrict__ gt, float* __restrict__ out) {
    extern __shared__ __align__(16) char smem_raw[];
    const int tid = threadIdx.x, bid = blockIdx.x;

    // --- phase C: fold m-chunk partials (blocks 0..119) + fp64 moments ---
    if (bid < 120) {
        float* comb = reinterpret_cast<float*>(smem_raw);     // [4][256]
        __shared__ double sm1[8], sm2[8];
        const int k = bid / 40, rem = bid % 40;
        const int n0 = rem * 256;
        const int r = tid >> 8, j = tid & 255;
        const int n = n0 + j;
        {
            float acc = 0.f;
            const int c0 = r * 40, cend = (r < 3) ? c0 + 40 : NCHUNK_M;
            for (int c = c0; c < cend; c++) acc += g_part[k][c][n];
            comb[r * 256 + j] = acc;
        }
        __syncthreads();
        if (tid < 256) {
            float acc = comb[tid] + comb[256 + tid] + comb[512 + tid] + comb[768 + tid];
            double x = 0.0;
            if (n0 + tid < NCORR) { g_raw[k][n0 + tid] = acc; x = (double)acc; }
            double s = x, sq = x * x;
#pragma unroll
            for (int o = 16; o; o >>= 1) {
                s  += __shfl_xor_sync(0xffffffffu, s,  o);
                sq += __shfl_xor_sync(0xffffffffu, sq, o);
            }
            if ((tid & 31) == 0) { sm1[tid >> 5] = s; sm2[tid >> 5] = sq; }
        }
        __syncthreads();
        if (tid < 32) {
            double s  = (tid < 8) ? sm1[tid] : 0.0;
            double sq = (tid < 8) ? sm2[tid] : 0.0;
#pragma unroll
            for (int o = 16; o; o >>= 1) {
                s  += __shfl_xor_sync(0xffffffffu, s,  o);
                sq += __shfl_xor_sync(0xffffffffu, sq, o);
            }
            if (tid == 0) { g_bs1[k][rem] = s; g_bs2[k][rem] = sq; }
        }
    }
    grid_sync();

    // --- phase D: every block folds stats redundantly ---
    __shared__ float sh_scale[3], sh_mean[3], sh_amb[3];
    __shared__ double sh_sums6[6];
    {
        const int w = tid >> 5, lane = tid & 31;
        if (w < 6) {
            double s = (lane < 5) ? g_s6[w][lane] : 0.0;
#pragma unroll
            for (int o = 16; o; o >>= 1) s += __shfl_xor_sync(0xffffffffu, s, o);
            if (lane == 0) sh_sums6[w] = s;
        }
        __syncthreads();
        if (w < 3) {
            double s1 = g_bs1[w][lane] + ((lane < 8) ? g_bs1[w][lane + 32] : 0.0);
            double s2 = g_bs2[w][lane] + ((lane < 8) ? g_bs2[w][lane + 32] : 0.0);
#pragma unroll
            for (int o = 16; o; o >>= 1) {
                s1 += __shfl_xor_sync(0xffffffffu, s1, o);
                s2 += __shfl_xor_sync(0xffffffffu, s2, o);
            }
            if (lane == 0) {
                double mean = s1 / NCORR;
                double var  = (s2 - s1 * s1 / NCORR) / (NCORR - 1);
                double sgn  = (sh_sums6[w] < 0.0) ? -1.0 : 1.0;
                sh_scale[w] = (float)(sgn * LOG2E / sqrt(var));
                sh_mean[w]  = (float)mean;
            }
        }
        if (tid >= 96 && tid < 99) sh_amb[tid - 96] = (float)(1.0e6 * sh_sums6[3 + (tid - 96)]);
    }
    __syncthreads();

    // --- phase E: build SoA templates (u, v) into smem ---
    float* s_u = reinterpret_cast<float*>(smem_raw);
    float* s_v = s_u + 10048;
    {
        const float sc0 = sh_scale[0], sc1 = sh_scale[1], sc2 = sh_scale[2];
        const float mv0 = sh_mean[0],  mv1 = sh_mean[1],  mv2 = sh_mean[2];
        for (int n = tid; n < NCORR; n += 1024) {
            float c0 = sc0 * (g_raw[0][n] - mv0);
            float c1 = sc1 * (g_raw[1][n] - mv1);
            float c2 = sc2 * (g_raw[2][n] - mv2);
            s_u[n] = (c0 - c1) * RSQRT2;
            s_v[n] = (c0 + c1 - 2.f * c2) * RSQRT6;
        }
    }
    __syncthreads();

    // --- phase F: theta-grid decode — exactly 1 task per warp ---
    {
        const int lane = tid & 31;
        const int task = bid * 32 + (tid >> 5);
        const int j = task >> 2, chunk = task & 3;
        const int base = chunk * 2500;
        float sn_, cs_;
        sincosf((float)((double)j * (TWOPI / MTHETA)), &sn_, &cs_);
        const float p = SQRT2F * cs_, q = SQRT2F * sn_;
        const ull pp = pk(p, p), qq = pk(q, q);
        const ull c128 = pk(128.f, 128.f);

        ull sA = 0ull, sB = 0ull, wA = 0ull, wB = 0ull;
        const int nb = base + 4 * lane;
        ull nfA = pk((float)nb, (float)(nb + 1));
        ull nfB = pk((float)(nb + 2), (float)(nb + 3));
        const ulonglong2* pu = reinterpret_cast<const ulonglong2*>(&s_u[nb]);
        const ulonglong2* pv = reinterpret_cast<const ulonglong2*>(&s_v[nb]);

#pragma unroll 4
        for (int it = 0; it < 19; it++) {         // 19*128 = 2432 of 2500
            ulonglong2 U = pu[it * 32];
            ulonglong2 V = pv[it * 32];
            ull zA = f2fma(pp, U.x, f2mul(qq, V.x));
            ull zB = f2fma(pp, U.y, f2mul(qq, V.y));
            float a, b;
            upk(zA, a, b); ull eA = pk(ex2(a), ex2(b));
            upk(zB, a, b); ull eB = pk(ex2(a), ex2(b));
            sA = f2add(sA, eA);  sB = f2add(sB, eB);
            wA = f2fma(eA, nfA, wA); wB = f2fma(eB, nfB, wB);
            nfA = f2add(nfA, c128);  nfB = f2add(nfB, c128);
        }
        if (lane < 17) {                          // tail: 68 samples
            const int n = base + 2432 + 4 * lane;
            ulonglong2 U = *reinterpret_cast<const ulonglong2*>(&s_u[n]);
            ulonglong2 V = *reinterpret_cast<const ulonglong2*>(&s_v[n]);
            ull ntA = pk((float)n, (float)(n + 1));
            ull ntB = pk((float)(n + 2), (float)(n + 3));
            ull zA = f2fma(pp, U.x, f2mul(qq, V.x));
            ull zB = f2fma(pp, U.y, f2mul(qq, V.y));
            float a, b;
            upk(zA, a, b); ull eA = pk(ex2(a), ex2(b));
            upk(zB, a, b); ull eB = pk(ex2(a), ex2(b));
            sA = f2add(sA, eA);  sB = f2add(sB, eB);
            wA = f2fma(eA, ntA, wA); wB = f2fma(eB, ntB, wB);
        }
        float a, b, s, w;
        ull st = f2add(sA, sB), wt = f2add(wA, wB);
        upk(st, a, b); s = a + b;
        upk(wt, a, b); w = a + b;
#pragma unroll
        for (int o = 16; o; o >>= 1) {
            s += __shfl_xor_sync(0xffffffffu, s, o);
            w += __shfl_xor_sync(0xffffffffu, w, o);
        }
        if (lane == 0) g_ps[j][chunk] = make_float2(s, w);
    }
    grid_sync();

    // --- phase G: gather per pixel (atan2 + lerp) ---
    {
        const float amb0 = sh_amb[0], amb1 = sh_amb[1], amb2 = sh_amb[2];
        const float inv_dt = (float)(MTHETA / TWOPI);
        const int px = bid * 1024 + tid;
        if (px < NPIX) {
            int idx = (int)rintf(gt[px]);
            idx = min(max(idx, 0), NCORR - 1);
            float x = __ldcg(&g_raw[0][idx]) + amb0;
            float y = __ldcg(&g_raw[1][idx]) + amb1;
            float z = __ldcg(&g_raw[2][idx]) + amb2;
            float pv = (x - y);
            float qv = (x + y - 2.f * z) * (RSQRT6 / RSQRT2);
            float th = atan2f(qv, pv);
            if (th < 0.f) th += (float)TWOPI;
            float g = th * inv_dt;
            int j0 = (int)g;
            float f = g - (float)j0;
            if (j0 >= MTHETA) j0 -= MTHETA;
            int j1 = j0 + 1; if (j1 >= MTHETA) j1 -= MTHETA;
            const float4* q0 = reinterpret_cast<const float4*>(&g_ps[j0][0]);
            const float4* q1 = reinterpret_cast<const float4*>(&g_ps[j1][0]);
            float4 u0 = __ldcg(&q0[0]), u1 = __ldcg(&q0[1]);
            float4 v0 = __ldcg(&q1[0]), v1 = __ldcg(&q1[1]);
            float S0 = u0.x + u0.z + u1.x + u1.z;
            float W0 = u0.y + u0.w + u1.y + u1.w;
            float S1 = v0.x + v0.z + v1.x + v1.z;
            float W1 = v0.y + v0.w + v1.y + v1.w;
            float F0 = W0 / S0, F1 = W1 / S1;
            out[px] = fmaf(f, F1 - F0, F0);
        }
    }
}

extern "C" void kernel_launch(void* const* d_in, const int* in_sizes, int n_in,
                              void* d_out, int out_size) {
    const float* gt  = (const float*)d_in[0];
    const float* Mod = (const float*)d_in[1];
    const float* Dem = (const float*)d_in[2];
    float* out = (float*)d_out;

    prep_kernel<<<90, 1024>>>(Mod, Dem);
    corr_kernel<<<1184, 128>>>();

    int smem = 98304;   // templates 80.4KB; 148 blocks -> 1/SM, spin-sync residency
    cudaFuncSetAttribute(tail_kernel, cudaFuncAttributeMaxDynamicSharedMemorySize, smem);
    tail_kernel<<<NBLK, 1024, smem>>>(gt, out);
}